// round 10
// baseline (speedup 1.0000x reference)
#include <cuda_runtime.h>
#include <math.h>

#define BATCH 2
#define NP    4096
#define HH    128
#define WW    128
#define KK    8
#define RAD   0.05f
#define RAD2  (RAD * RAD)
#define TILE  4
#define TX    (WW / TILE)    // 32
#define TYN   (HH / TILE)    // 32
#define NTILES (TX * TYN)    // 1024
#define NCTA  (TX * TYN * BATCH)  // 2048
#define LPP   4
#define NPIX  (TILE * TILE)  // 16
#define THREADS (NPIX * LPP) // 64
#define PTS_PER_CTA ((BATCH * NP) / NCTA)  // 4
#define CAP   1024           // per-tile list capacity (~25x margin)
#define CHUNK 256

#define ZINF 3.0e38f

// Global scratch (no cudaMalloc allowed)
__device__ int      g_cnt[BATCH * NTILES];        // zero-init; reset in-kernel
__device__ float4   g_list[BATCH * NTILES * CAP]; // 32 MB
__device__ unsigned g_arrive = 0;
__device__ unsigned g_epoch  = 0;                 // monotonic across replays

__global__ void __launch_bounds__(THREADS, 16) raster_fused(
        const float* __restrict__ pts,
        const float* __restrict__ Rm,
        const float* __restrict__ Tv,
        const float* __restrict__ Fc,
        float* __restrict__ out) {
    __shared__ float4 sc[CHUNK];   // 4 KB
    __shared__ int s_n;

    const int bx = blockIdx.x, by = blockIdx.y, b = blockIdx.z;
    const int cta = bx + TX * (by + TYN * b);
    const int tid = threadIdx.x;

    // ====== Phase 1: transform + bin, spread over ALL CTAs (4 pts each) ======
    if (tid < PTS_PER_CTA) {
        int t = cta * PTS_PER_CTA + tid;
        int pb = t / NP;
        int p  = t - pb * NP;
        float p0 = pts[t * 3 + 0];
        float p1 = pts[t * 3 + 1];
        float p2 = pts[t * 3 + 2];
        const float* Rb = Rm + pb * 9;
        const float* Tb = Tv + pb * 3;

        // row-vector: v[j] = sum_i p[i]*R[i][j] + T[j]
        float xv = p0 * Rb[0] + p1 * Rb[3] + p2 * Rb[6] + Tb[0];
        float yv = p0 * Rb[1] + p1 * Rb[4] + p2 * Rb[7] + Tb[1];
        float zv = p0 * Rb[2] + p1 * Rb[5] + p2 * Rb[8] + Tb[2];

        float f = Fc[pb];
        float x = f * xv / zv;   // IEEE div, matches reference
        float y = f * yv / zv;

        if (zv > 0.0f) {
            float lox = 64.0f * (1.0f - x - RAD) - 0.5f;
            float hix = 64.0f * (1.0f - x + RAD) - 0.5f;
            float loy = 64.0f * (1.0f - y - RAD) - 0.5f;
            float hiy = 64.0f * (1.0f - y + RAD) - 0.5f;
            if (hix >= 0.0f && lox <= (float)(WW - 1) &&
                hiy >= 0.0f && loy <= (float)(HH - 1)) {
                int ix0 = max(0, (int)floorf(fmaxf(lox, 0.0f)));
                int ix1 = min(WW - 1, (int)ceilf(fminf(hix, (float)(WW - 1))));
                int iy0 = max(0, (int)floorf(fmaxf(loy, 0.0f)));
                int iy1 = min(HH - 1, (int)ceilf(fminf(hiy, (float)(HH - 1))));
                if (ix0 <= ix1 && iy0 <= iy1) {
                    int tx0 = ix0 / TILE, tx1 = ix1 / TILE;
                    int ty0 = iy0 / TILE, ty1 = iy1 / TILE;
                    float4 rec = make_float4(x, y, zv, (float)p);
                    for (int ty = ty0; ty <= ty1; ty++)
                        for (int tx = tx0; tx <= tx1; tx++) {
                            int tile = pb * NTILES + ty * TX + tx;
                            int pos = atomicAdd(&g_cnt[tile], 1);
                            if (pos < CAP) g_list[tile * CAP + pos] = rec;
                        }
                }
            }
        }
    }

    // ====== Grid-wide barrier (2048 CTAs, single co-resident wave) ===========
    __threadfence();
    __syncthreads();
    if (tid == 0) {
        unsigned e = *(volatile unsigned*)&g_epoch;
        __threadfence();
        unsigned a = atomicAdd(&g_arrive, 1u);
        if (a == NCTA - 1) {
            g_arrive = 0;
            __threadfence();
            atomicAdd(&g_epoch, 1u);
        } else {
            while (*(volatile unsigned*)&g_epoch == e) __nanosleep(64);
        }
        __threadfence();
    }
    __syncthreads();

    // ====== Phase 2: raster — 4 lanes per pixel ==============================
    const int tile = b * NTILES + by * TX + bx;
    if (tid == 0) {
        int c = g_cnt[tile];
        s_n = min(c, CAP);
        g_cnt[tile] = 0;           // reset for next graph replay (own counter)
    }
    __syncthreads();
    const int n = s_n;
    const float4* __restrict__ list = g_list + tile * CAP;

    const int grp = tid >> 2;      // pixel 0..15
    const int sub = tid & 3;       // lane within pixel
    const int lx = grp & (TILE - 1), ly = grp / TILE;
    const int px = bx * TILE + lx;
    const int py = by * TILE + ly;
    const float gx = 1.0f - (px + 0.5f) * (1.0f / 64.0f);
    const float gy = 1.0f - (py + 0.5f) * (1.0f / 64.0f);

    float zb[KK];
#pragma unroll
    for (int k = 0; k < KK; k++) zb[k] = ZINF;

    // ---- Pass 1 (chunked): branch-free FMNMX ladder, lane scans j%4==sub ----
    for (int base = 0; base < n; base += CHUNK) {
        int m = min(CHUNK, n - base);
        __syncthreads();
        for (int i = tid; i < m; i += THREADS) sc[i] = list[base + i];
        __syncthreads();
        for (int j = sub; j < m; j += LPP) {
            float4 c = sc[j];
            float dx = gx - c.x;
            float dy = gy - c.y;
            float d2 = fmaf(dx, dx, dy * dy);
            float key = (d2 < RAD2) ? c.z : ZINF;
#pragma unroll
            for (int k = 0; k < KK; k++) {
                float lo = fminf(zb[k], key);
                key = fmaxf(zb[k], key);
                zb[k] = lo;
            }
        }
    }

    // ---- merge 4 sorted lists: two bitonic-merge rounds (xor 1, xor 2) ------
#pragma unroll
    for (int d = 1; d <= 2; d <<= 1) {
        float L[KK];
#pragma unroll
        for (int k = 0; k < KK; k++) {
            float bk = __shfl_xor_sync(0xffffffffu, zb[KK - 1 - k], d);
            L[k] = fminf(zb[k], bk);          // lower half of bitonic merge
        }
#define CE(a, b2) { float lo = fminf(L[a], L[b2]); float hi = fmaxf(L[a], L[b2]); L[a] = lo; L[b2] = hi; }
        CE(0, 4) CE(1, 5) CE(2, 6) CE(3, 7)
        CE(0, 2) CE(1, 3) CE(4, 6) CE(5, 7)
        CE(0, 1) CE(2, 3) CE(4, 5) CE(6, 7)
#undef CE
#pragma unroll
        for (int k = 0; k < KK; k++) zb[k] = L[k];
    }
    const float z7 = zb[KK - 1];

    float db[KK], ib[KK];
#pragma unroll
    for (int k = 0; k < KK; k++) { db[k] = -1.0f; ib[k] = -1.0f; }

    // ---- Pass 2 (chunked): sparse equality fill of d2/idx (z distinct) ------
    for (int base = 0; base < n; base += CHUNK) {
        int m = min(CHUNK, n - base);
        if (n > CHUNK) {                      // restage only if list didn't fit
            __syncthreads();
            for (int i = tid; i < m; i += THREADS) sc[i] = list[base + i];
            __syncthreads();
        }
        for (int j = sub; j < m; j += LPP) {
            float4 c = sc[j];
            float dx = gx - c.x;
            float dy = gy - c.y;
            float d2 = fmaf(dx, dx, dy * dy);
            if (d2 < RAD2 && c.z <= z7) {
#pragma unroll
                for (int k = 0; k < KK; k++) {
                    if (c.z == zb[k]) { db[k] = d2; ib[k] = c.w; }
                }
            }
        }
    }

    // ---- combine lane fills (unfilled = -1, filled >= 0 => max) -------------
#pragma unroll
    for (int d = 1; d <= 2; d <<= 1) {
#pragma unroll
        for (int k = 0; k < KK; k++) {
            db[k] = fmaxf(db[k], __shfl_xor_sync(0xffffffffu, db[k], d));
            ib[k] = fmaxf(ib[k], __shfl_xor_sync(0xffffffffu, ib[k], d));
        }
    }

    // ---- Output: [idx | zbuf | dists], each [B,H,W,K]; lanes split k --------
    const int N = BATCH * HH * WW * KK;
    const int obase = ((b * HH + py) * WW + px) * KK;
#pragma unroll
    for (int k2 = 0; k2 < KK / LPP; k2++) {
        int k = sub * (KK / LPP) + k2;
        bool v = zb[k] < ZINF;
        out[obase + k]         = v ? ib[k] : -1.0f;
        out[N + obase + k]     = v ? zb[k] : -1.0f;
        out[2 * N + obase + k] = v ? db[k] : -1.0f;
    }
}

// ---------------------------------------------------------------------------
extern "C" void kernel_launch(void* const* d_in, const int* in_sizes, int n_in,
                              void* d_out, int out_size) {
    const float* pts = (const float*)d_in[0];
    const float* Rm  = (const float*)d_in[1];
    const float* Tv  = (const float*)d_in[2];
    const float* Fc  = (const float*)d_in[3];
    float* out = (float*)d_out;

    raster_fused<<<dim3(TX, TYN, BATCH), THREADS>>>(pts, Rm, Tv, Fc, out);
}